// round 13
// baseline (speedup 1.0000x reference)
#include <cuda_runtime.h>
#include <cstdint>
#include <cstddef>

static constexpr int Bn = 16;
static constexpr int Nn = 4096;
static constexpr int Cn = 256;
static constexpr int Hn = 4;
static constexpr int Mn = Bn * Nn;   // 65536 rows

// ---------------- scratch (static __device__ per allocation rules) ----------
__device__ float g_qkv [(size_t)Mn * 512];   // [s | v], 512 wide
__device__ float g_wi  [(size_t)Mn * Cn];
__device__ float g_w   [(size_t)Mn * Cn];
__device__ float g_outs[(size_t)Mn * Cn];
__device__ float g_h1  [(size_t)Mn * 512];
__device__ float g_colsum[Bn * Cn];
__device__ float g_sumws [Bn * Hn * Nn];
__device__ float g_rw2   [Bn * Hn * Nn];
__device__ float g_Pi    [Bn * Hn * Nn];
__device__ float g_S   [Bn * Hn];
__device__ float g_num [Bn * Hn];
__device__ float g_attn[Bn * Hn];
__device__ float g_Wc[Cn * Cn];      // out_proj_w @ tssa_out_w
__device__ float g_bc[Cn];           // out_proj_w @ tssa_out_b + out_proj_b
__device__ float g_Wd[512 * Cn];     // ffn1_m @ Wc
__device__ float g_b2[512];          // ffn1_b + ffn1_m @ bc
__device__ float g_Wqv[512 * Cn];    // [Wq+Wk ; Wv] packed, (h d) layout
__device__ float g_bqv[512];

// ---------------- helpers ---------------------------------------------------
__device__ __forceinline__ void mma_tf32(float* d, const uint32_t* a, const uint32_t* b) {
    asm volatile(
        "mma.sync.aligned.m16n8k8.row.col.f32.tf32.tf32.f32 "
        "{%0,%1,%2,%3}, {%4,%5,%6,%7}, {%8,%9}, {%0,%1,%2,%3};\n"
        : "+f"(d[0]), "+f"(d[1]), "+f"(d[2]), "+f"(d[3])
        : "r"(a[0]), "r"(a[1]), "r"(a[2]), "r"(a[3]), "r"(b[0]), "r"(b[1]));
}

__device__ __forceinline__ void cp16(uint32_t saddr, const void* g) {
    asm volatile("cp.async.cg.shared.global [%0], [%1], 16;\n" :: "r"(saddr), "l"(g));
}

// block-wide sum over 256 threads; result valid on thread 0
__device__ __forceinline__ float blockSum256(float v) {
    __shared__ float sm[8];
    #pragma unroll
    for (int o = 16; o > 0; o >>= 1) v += __shfl_xor_sync(0xffffffffu, v, o);
    int lane = threadIdx.x & 31, warp = threadIdx.x >> 5;
    if (lane == 0) sm[warp] = v;
    __syncthreads();
    float r = 0.f;
    if (threadIdx.x < 8) {
        r = sm[threadIdx.x];
        #pragma unroll
        for (int o = 4; o > 0; o >>= 1) r += __shfl_xor_sync(0xffu, r, o);
    }
    __syncthreads();
    return r;
}

// ---------------- tf32 GEMM: C[M,Nout] = A[M,K] @ W[Nout,K]^T + bias (+Rsd) --
// BM=128, BN=128, BK=32, 256 threads (8 warps 2x4), warp tile 64x32.
// cp.async double-buffered. fp32 raw in SMEM; HMMA truncates to tf32.
// AMODE 0: plain A/W (lda=ldw=K).
// AMODE 1: split ffn1 — k<256: A (lda 256) + W (ldw 512); k>=256: A2 (lda 256)
//          + W2 (ldw 256). All cp.async (A2 is pre-scaled by scaleout pass).
// COLSUM: epilogue accumulates per-column sum of C^2 into g_colsum[batch].
static constexpr int STAGE_F = 128 * 36;   // floats per tile per stage

template <int AMODE, bool RES, bool COLSUM>
__global__ __launch_bounds__(256, 2) void gemm_tf32(
    const float* __restrict__ A, const float* __restrict__ A2,
    const float* __restrict__ W, const float* __restrict__ W2,
    const float* __restrict__ bias, const float* __restrict__ Rsd,
    float* __restrict__ C, int K, int Nout)
{
    extern __shared__ float smem[];
    float* Asm = smem;                     // [2][128][36]
    float* Bsm = smem + 2 * STAGE_F;       // [2][128][36]

    const int tid  = threadIdx.x;
    const int m0   = blockIdx.x << 7;
    const int n0   = blockIdx.y << 7;
    const int warp = tid >> 5, lane = tid & 31;
    const int wm = (warp >> 2) << 6;   // 0 or 64
    const int wn = (warp & 3) << 5;    // 0,32,64,96
    const int g  = lane >> 2, tg = lane & 3;

    const uint32_t sA = (uint32_t)__cvta_generic_to_shared(Asm);
    const uint32_t sB = (uint32_t)__cvta_generic_to_shared(Bsm);

    const int lrow = tid >> 3;          // base row, +32 per chunk
    const int lc4  = (tid & 7) << 2;    // 0,4,...,28

    float acc[4][4][4];
    #pragma unroll
    for (int i = 0; i < 4; i++)
        #pragma unroll
        for (int j = 0; j < 4; j++)
            #pragma unroll
            for (int r = 0; r < 4; r++) acc[i][j][r] = 0.f;

    const int KT = K >> 5;

    auto loadStage = [&](int kt, int s) {
        int kb = kt << 5;
        const float* Ap; const float* Wp;
        int kbA, kbW, ldA, ldW;
        if (AMODE == 1) {
            if (kb < 256) { Ap = A;  kbA = kb;       ldA = 256; Wp = W;  kbW = kb;       ldW = 512; }
            else          { Ap = A2; kbA = kb - 256; ldA = 256; Wp = W2; kbW = kb - 256; ldW = 256; }
        } else {
            Ap = A; kbA = kb; ldA = K; Wp = W; kbW = kb; ldW = K;
        }
        #pragma unroll
        for (int i = 0; i < 4; i++) {
            int row = lrow + (i << 5);
            uint32_t so = (uint32_t)((s * STAGE_F + row * 36 + lc4) << 2);
            cp16(sA + so, Ap + (size_t)(m0 + row) * ldA + kbA + lc4);
            cp16(sB + so, Wp + (size_t)(n0 + row) * ldW + kbW + lc4);
        }
        asm volatile("cp.async.commit_group;\n" ::);
    };

    loadStage(0, 0);

    for (int kt = 0; kt < KT; kt++) {
        const int cur = kt & 1;
        if (kt + 1 < KT) {
            loadStage(kt + 1, (kt + 1) & 1);
            asm volatile("cp.async.wait_group 1;\n" ::);
        } else {
            asm volatile("cp.async.wait_group 0;\n" ::);
        }
        __syncthreads();

        const float* Ac = Asm + cur * STAGE_F;
        const float* Bc = Bsm + cur * STAGE_F;

        #pragma unroll
        for (int ks = 0; ks < 4; ks++) {
            const int k0 = ks << 3;
            uint32_t a[4][4], bf[4][2];
            #pragma unroll
            for (int mf = 0; mf < 4; mf++) {
                int r = wm + (mf << 4);
                a[mf][0] = __float_as_uint(Ac[(r + g    ) * 36 + k0 + tg]);
                a[mf][1] = __float_as_uint(Ac[(r + g + 8) * 36 + k0 + tg]);
                a[mf][2] = __float_as_uint(Ac[(r + g    ) * 36 + k0 + tg + 4]);
                a[mf][3] = __float_as_uint(Ac[(r + g + 8) * 36 + k0 + tg + 4]);
            }
            #pragma unroll
            for (int nf = 0; nf < 4; nf++) {
                int c = wn + (nf << 3);
                bf[nf][0] = __float_as_uint(Bc[(c + g) * 36 + k0 + tg]);
                bf[nf][1] = __float_as_uint(Bc[(c + g) * 36 + k0 + tg + 4]);
            }
            #pragma unroll
            for (int mf = 0; mf < 4; mf++)
                #pragma unroll
                for (int nf = 0; nf < 4; nf++)
                    mma_tf32(acc[mf][nf], a[mf], bf[nf]);
        }
        __syncthreads();
    }

    // epilogue
    float* cs = smem;                  // 128-col squared-sum accumulator
    if (COLSUM) {
        if (tid < 128) cs[tid] = 0.f;
        __syncthreads();
    }
    float csl[4][2];
    if (COLSUM) {
        #pragma unroll
        for (int nf = 0; nf < 4; nf++) { csl[nf][0] = 0.f; csl[nf][1] = 0.f; }
    }

    #pragma unroll
    for (int mf = 0; mf < 4; mf++) {
        #pragma unroll
        for (int nf = 0; nf < 4; nf++) {
            int r = m0 + wm + (mf << 4) + g;
            int c = n0 + wn + (nf << 3) + (tg << 1);
            float b0 = bias[c], b1 = bias[c + 1];
            float o0 = acc[mf][nf][0] + b0, o1 = acc[mf][nf][1] + b1;
            float o2 = acc[mf][nf][2] + b0, o3 = acc[mf][nf][3] + b1;
            size_t p0 = (size_t)r * Nout + c;
            size_t p1 = (size_t)(r + 8) * Nout + c;
            if (RES) {
                o0 += Rsd[p0]; o1 += Rsd[p0 + 1];
                o2 += Rsd[p1]; o3 += Rsd[p1 + 1];
            }
            if (COLSUM) {
                csl[nf][0] += o0 * o0 + o2 * o2;
                csl[nf][1] += o1 * o1 + o3 * o3;
            }
            *(float2*)(C + p0) = make_float2(o0, o1);
            *(float2*)(C + p1) = make_float2(o2, o3);
        }
    }

    if (COLSUM) {
        #pragma unroll
        for (int nf = 0; nf < 4; nf++) {
            int cn = wn + (nf << 3) + (tg << 1);
            atomicAdd(&cs[cn], csl[nf][0]);
            atomicAdd(&cs[cn + 1], csl[nf][1]);
        }
        __syncthreads();
        if (tid < 128)
            atomicAdd(&g_colsum[((m0 >> 12) << 8) + n0 + tid], cs[tid]);
    }
}

// ---------------- tiled small fp32 GEMM, split-K: C += A @ B ----------------
// 64x64 tiles, BK=32, 256 threads, 4x4 per thread, blockIdx.z = K slice.
__global__ __launch_bounds__(256) void gemm_small(
    const float* __restrict__ A, int lda,
    const float* __restrict__ B, int ldb,
    float* __restrict__ Cc, int ldc, int K)
{
    __shared__ float As[32][65];
    __shared__ float Bs[32][65];
    int tid = threadIdx.x;
    int m0 = blockIdx.y << 6, n0 = blockIdx.x << 6;
    int kslice = K / gridDim.z;
    int kbeg = blockIdx.z * kslice, kend = kbeg + kslice;
    int ty = tid >> 4, tx = tid & 15;
    float acc[4][4] = {};
    for (int k0 = kbeg; k0 < kend; k0 += 32) {
        #pragma unroll
        for (int i = 0; i < 8; i++) {
            int idx = tid + i * 256;           // 0..2047
            int r = idx >> 5, c = idx & 31;    // A tile: row r, k c
            As[c][r] = A[(size_t)(m0 + r) * lda + k0 + c];
        }
        #pragma unroll
        for (int i = 0; i < 8; i++) {
            int idx = tid + i * 256;
            int r = idx >> 6, c = idx & 63;    // B tile: k r, col c
            Bs[r][c] = B[(size_t)(k0 + r) * ldb + n0 + c];
        }
        __syncthreads();
        #pragma unroll
        for (int kk = 0; kk < 32; kk++) {
            float a[4], b[4];
            #pragma unroll
            for (int i = 0; i < 4; i++) a[i] = As[kk][ty * 4 + i];
            #pragma unroll
            for (int j = 0; j < 4; j++) b[j] = Bs[kk][tx * 4 + j];
            #pragma unroll
            for (int i = 0; i < 4; i++)
                #pragma unroll
                for (int j = 0; j < 4; j++) acc[i][j] += a[i] * b[j];
        }
        __syncthreads();
    }
    #pragma unroll
    for (int i = 0; i < 4; i++)
        #pragma unroll
        for (int j = 0; j < 4; j++)
            atomicAdd(&Cc[(size_t)(m0 + ty * 4 + i) * ldc + n0 + tx * 4 + j], acc[i][j]);
}

// ---------------- pack [Wq+Wk ; Wv] and biases ------------------------------
__global__ void extract_qkv_kernel(const float* __restrict__ w, const float* __restrict__ b) {
    int idx = blockIdx.x * 256 + threadIdx.x;    // 0..131071
    int c = idx >> 8, k = idx & 255;             // c: 0..511 -> but only 0..255 used for rows
    if (c < 256) {
        int h = c >> 6, d = c & 63;
        int base = (h * 192 + d * 3) * 256 + k;
        g_Wqv[(size_t)c * 256 + k] = w[base] + w[base + 256];
        g_Wqv[(size_t)(256 + c) * 256 + k] = w[base + 512];
    }
    if (idx < 256) {
        int h = idx >> 6, d = idx & 63;
        int bb = h * 192 + d * 3;
        g_bqv[idx] = b[bb] + b[bb + 1];
        g_bqv[256 + idx] = b[bb + 2];
    }
}

// bc = out_proj_w @ tssa_out_b + out_proj_b
__global__ void combine_b_kernel(const float* __restrict__ opw,
                                 const float* __restrict__ ab,
                                 const float* __restrict__ ob) {
    int i = threadIdx.x;
    float s = ob[i];
    for (int k = 0; k < 256; k++) s += opw[i * 256 + k] * ab[k];
    g_bc[i] = s;
}
// b2[i] = ffn1_b[i] + sum_k ffn1_w[i][256+k] * bc[k]
__global__ void combine_b2_kernel(const float* __restrict__ ffn1w,
                                  const float* __restrict__ ffn1b) {
    int i = blockIdx.x * 256 + threadIdx.x;
    float s = ffn1b[i];
    for (int k = 0; k < 256; k++) s += ffn1w[i * 512 + 256 + k] * g_bc[k];
    g_b2[i] = s;
}

// ---------------- zero accumulators + split-K outputs -----------------------
__global__ void zero_kernel() {
    int i = blockIdx.x * 256 + threadIdx.x;
    if (i < Bn * Cn) g_colsum[i] = 0.f;
    if (i < Bn * Hn) { g_S[i] = 0.f; g_num[i] = 0.f; }
    if (i < Cn * Cn) g_Wc[i] = 0.f;
    if (i < 512 * Cn) g_Wd[i] = 0.f;
}

// ---------------- RoPE + (s + v)/3 combine (rope(q)+rope(k) = rope(q+k)) ----
__global__ void rope_kernel(const float* __restrict__ enc) {
    int gid = blockIdx.x * 256 + threadIdx.x;       // (m, h, dpair)
    int dp = gid & 31;
    int h  = (gid >> 5) & 3;
    int m  = gid >> 7;
    int b  = m >> 12, n = m & 4095;

    const float* sv = g_qkv + (size_t)m * 512;
    float2 s = *(const float2*)(sv + h * 64 + dp * 2);
    float2 v = *(const float2*)(sv + 256 + h * 64 + dp * 2);

    size_t eb = ((size_t)b * 4096 + n) * 64 + dp * 2;
    float2 e0 = *(const float2*)(enc + eb);
    float2 e1 = *(const float2*)(enc + 4194304 + eb);  // 16*4096*64

    float sr0 = s.x * e0.x - s.y * e1.x;
    float sr1 = s.y * e0.y + s.x * e1.y;

    const float third = 1.f / 3.f;
    float2 o;
    o.x = (sr0 + v.x) * third;
    o.y = (sr1 + v.y) * third;
    *(float2*)(g_wi + (size_t)m * 256 + h * 64 + dp * 2) = o;
}

// ---------------- per-(row, head) sums (invnorm fused) ----------------------
__global__ void rowsums_kernel() {
    int warp = threadIdx.x >> 5, lane = threadIdx.x & 31;
    int m = blockIdx.x * 8 + warp;
    int b = m >> 12, n = m & 4095;
    const float4* w4 = (const float4*)g_w;
    float4 v0 = w4[(size_t)m * 64 + lane * 2];
    float4 v1 = w4[(size_t)m * 64 + lane * 2 + 1];
    float vals[8] = {v0.x, v0.y, v0.z, v0.w, v1.x, v1.y, v1.z, v1.w};
    int cbase = (b << 8) + lane * 8;
    float s1 = 0.f, s2 = 0.f;
    #pragma unroll
    for (int j = 0; j < 8; j++) {
        float wv = vals[j];
        float iv = 1.f / fmaxf(sqrtf(g_colsum[cbase + j]), 1e-12f);
        s2 += wv * wv;
        float t = wv * iv;
        s1 += t * t;
    }
    #pragma unroll
    for (int o = 4; o > 0; o >>= 1) {
        s1 += __shfl_xor_sync(0xffffffffu, s1, o);
        s2 += __shfl_xor_sync(0xffffffffu, s2, o);
    }
    if ((lane & 7) == 0) {
        int h = lane >> 3;
        g_sumws[((size_t)((b << 2) + h)) * 4096 + n] = s1;
        g_rw2  [((size_t)((b << 2) + h)) * 4096 + n] = s2;
    }
}

// ---------------- Pi = softmax over heads; accumulate S and num -------------
__global__ void pi_kernel(const float* __restrict__ temp) {
    int b = blockIdx.x >> 4;
    int n = ((blockIdx.x & 15) << 8) + threadIdx.x;
    float sw[4], p[4], r2[4];
    #pragma unroll
    for (int h = 0; h < 4; h++) {
        size_t idx = (size_t)((b << 2) + h) * 4096 + n;
        sw[h] = g_sumws[idx] * temp[h];
        r2[h] = g_rw2[idx];
    }
    float mx = fmaxf(fmaxf(sw[0], sw[1]), fmaxf(sw[2], sw[3]));
    float s = 0.f;
    #pragma unroll
    for (int h = 0; h < 4; h++) { p[h] = expf(sw[h] - mx); s += p[h]; }
    float inv = 1.f / s;
    #pragma unroll
    for (int h = 0; h < 4; h++) {
        p[h] *= inv;
        g_Pi[(size_t)((b << 2) + h) * 4096 + n] = p[h];
    }
    for (int h = 0; h < 4; h++) {
        float t1 = blockSum256(p[h]);
        float t2 = blockSum256(p[h] * r2[h]);
        if (threadIdx.x == 0) {
            atomicAdd(&g_S[(b << 2) + h], t1);
            atomicAdd(&g_num[(b << 2) + h], t2);
        }
    }
}

__global__ void attn_kernel() {
    int i = threadIdx.x;
    if (i < Bn * Hn) {
        float d = g_num[i] / (g_S[i] + 1e-8f);
        g_attn[i] = 1.f / (1.f + d);
    }
}

// ---------------- out = -w * Pi * attn --------------------------------------
__global__ void scaleout_kernel() {
    int idx = blockIdx.x * 256 + threadIdx.x;   // float4 index
    int m = idx >> 6, c4 = idx & 63;
    int b = m >> 12, n = m & 4095;
    int h = c4 >> 4;
    float sc = -g_Pi[(size_t)((b << 2) + h) * 4096 + n] * g_attn[(b << 2) + h];
    float4 v = ((const float4*)g_w)[idx];
    v.x *= sc; v.y *= sc; v.z *= sc; v.w *= sc;
    ((float4*)g_outs)[idx] = v;
}

// ---------------- LayerNorm(512) + exact GELU, in place on g_h1 -------------
__global__ void lngelu_kernel(const float* __restrict__ gain, const float* __restrict__ beta) {
    int warp = threadIdx.x >> 5, lane = threadIdx.x & 31;
    int m = blockIdx.x * 8 + warp;
    float4* row = (float4*)(g_h1 + (size_t)m * 512);
    float v[16];
    #pragma unroll
    for (int i = 0; i < 4; i++) {
        float4 t = row[i * 32 + lane];
        v[i * 4 + 0] = t.x; v[i * 4 + 1] = t.y; v[i * 4 + 2] = t.z; v[i * 4 + 3] = t.w;
    }
    float s = 0.f;
    #pragma unroll
    for (int j = 0; j < 16; j++) s += v[j];
    #pragma unroll
    for (int o = 16; o > 0; o >>= 1) s += __shfl_xor_sync(0xffffffffu, s, o);
    float mu = s * (1.f / 512.f);
    float var = 0.f;
    #pragma unroll
    for (int j = 0; j < 16; j++) { float d = v[j] - mu; var += d * d; }
    #pragma unroll
    for (int o = 16; o > 0; o >>= 1) var += __shfl_xor_sync(0xffffffffu, var, o);
    float rstd = rsqrtf(var * (1.f / 512.f) + 1e-5f);
    #pragma unroll
    for (int i = 0; i < 4; i++) {
        float4 gg = ((const float4*)gain)[i * 32 + lane];
        float4 bb = ((const float4*)beta)[i * 32 + lane];
        float gv[4] = {gg.x, gg.y, gg.z, gg.w};
        float bv[4] = {bb.x, bb.y, bb.z, bb.w};
        float4 out;
        float* op = (float*)&out;
        #pragma unroll
        for (int j = 0; j < 4; j++) {
            float ln = (v[i * 4 + j] - mu) * rstd * gv[j] + bv[j];
            op[j] = 0.5f * ln * (1.f + erff(ln * 0.70710678118654752f));
        }
        row[i * 32 + lane] = out;
    }
}

// ---------------- host-side orchestration -----------------------------------
extern "C" void kernel_launch(void* const* d_in, const int* in_sizes, int n_in,
                              void* d_out, int out_size) {
    const float* x       = (const float*)d_in[0];
    const float* enc     = (const float*)d_in[1];
    const float* Wqkv_w  = (const float*)d_in[2];
    const float* Wqkv_b  = (const float*)d_in[3];
    const float* tqkv_w  = (const float*)d_in[4];
    const float* tqkv_b  = (const float*)d_in[5];
    const float* temp    = (const float*)d_in[6];
    const float* tout_w  = (const float*)d_in[7];
    const float* tout_b  = (const float*)d_in[8];
    const float* oproj_w = (const float*)d_in[9];
    const float* oproj_b = (const float*)d_in[10];
    const float* ffn1_w  = (const float*)d_in[11];
    const float* ffn1_b  = (const float*)d_in[12];
    const float* ln_g    = (const float*)d_in[13];
    const float* ln_b    = (const float*)d_in[14];
    const float* ffn2_w  = (const float*)d_in[15];
    const float* ffn2_b  = (const float*)d_in[16];
    float* out = (float*)d_out;

    float *p_qkv, *p_wi, *p_w, *p_outs, *p_h1, *p_Wc, *p_Wd, *p_b2, *p_Wqv, *p_bqv;
    cudaGetSymbolAddress((void**)&p_qkv,  g_qkv);
    cudaGetSymbolAddress((void**)&p_wi,   g_wi);
    cudaGetSymbolAddress((void**)&p_w,    g_w);
    cudaGetSymbolAddress((void**)&p_outs, g_outs);
    cudaGetSymbolAddress((void**)&p_h1,   g_h1);
    cudaGetSymbolAddress((void**)&p_Wc,   g_Wc);
    cudaGetSymbolAddress((void**)&p_Wd,   g_Wd);
    cudaGetSymbolAddress((void**)&p_b2,   g_b2);
    cudaGetSymbolAddress((void**)&p_Wqv,  g_Wqv);
    cudaGetSymbolAddress((void**)&p_bqv,  g_bqv);

    const int SMEM = 4 * STAGE_F * sizeof(float);   // 73728 bytes
    static bool attr_set = false;
    if (!attr_set) {
        cudaFuncSetAttribute(gemm_tf32<0, false, false>, cudaFuncAttributeMaxDynamicSharedMemorySize, SMEM);
        cudaFuncSetAttribute(gemm_tf32<0, false, true >, cudaFuncAttributeMaxDynamicSharedMemorySize, SMEM);
        cudaFuncSetAttribute(gemm_tf32<1, false, false>, cudaFuncAttributeMaxDynamicSharedMemorySize, SMEM);
        cudaFuncSetAttribute(gemm_tf32<0, true,  false>, cudaFuncAttributeMaxDynamicSharedMemorySize, SMEM);
        attr_set = true;
    }

    zero_kernel<<<512, 256>>>();
    extract_qkv_kernel<<<512, 256>>>(Wqkv_w, Wqkv_b);
    // Wc = out_proj_w @ tssa_out_w   (split-K x4, accumulated)
    gemm_small<<<dim3(4, 4, 4), 256>>>(oproj_w, 256, tout_w, 256, p_Wc, 256, 256);
    combine_b_kernel<<<1, 256>>>(oproj_w, tout_b, oproj_b);
    // Wd = ffn1_m @ Wc               (split-K x4; ffn1_m = ffn1_w cols 256..511)
    gemm_small<<<dim3(4, 8, 4), 256>>>(ffn1_w + 256, 512, p_Wc, 256, p_Wd, 256, 256);
    combine_b2_kernel<<<2, 256>>>(ffn1_w, ffn1_b);

    // [s|v] = x @ [Ws;Wv]^T + b     (rope linearity: N=512 instead of 768)
    gemm_tf32<0, false, false><<<dim3(512, 4), 256, SMEM>>>(
        x, nullptr, p_Wqv, nullptr, p_bqv, nullptr, p_qkv, 256, 512);
    // RoPE(s) + v -> w_input
    rope_kernel<<<32768, 256>>>(enc);
    // w = w_input @ tssa_qkv^T + b   (+ fused column sum of w^2)
    gemm_tf32<0, false, true><<<dim3(512, 2), 256, SMEM>>>(
        p_wi, nullptr, tqkv_w, nullptr, tqkv_b, nullptr, p_w, 256, 256);
    // TSSA reductions (invnorm fused into rowsums)
    rowsums_kernel<<<8192, 256>>>();
    pi_kernel<<<256, 256>>>(temp);
    attn_kernel<<<1, 64>>>();
    scaleout_kernel<<<16384, 256>>>();
    // h1 = x @ ffn1_x^T + outs @ Wd^T + b2   (msg GEMM folded; all cp.async)
    gemm_tf32<1, false, false><<<dim3(512, 4), 256, SMEM>>>(
        x, p_outs, ffn1_w, p_Wd, p_b2, nullptr, p_h1, 512, 512);
    // LN + exact GELU in place
    lngelu_kernel<<<8192, 256>>>(ln_g, ln_b);
    // out = x + g @ ffn2^T + b
    gemm_tf32<0, true, false><<<dim3(512, 2), 256, SMEM>>>(
        p_h1, nullptr, ffn2_w, nullptr, ffn2_b, x, out, 512, 256);
}

// round 14
// speedup vs baseline: 1.6089x; 1.6089x over previous
#include <cuda_runtime.h>
#include <cstdint>
#include <cstddef>

static constexpr int Bn = 16;
static constexpr int Nn = 4096;
static constexpr int Cn = 256;
static constexpr int Hn = 4;
static constexpr int Mn = Bn * Nn;   // 65536 rows

// ---------------- scratch (static __device__ per allocation rules) ----------
__device__ float g_qkv [(size_t)Mn * 512];   // [s | v], 512 wide
__device__ float g_wi  [(size_t)Mn * Cn];
__device__ float g_w   [(size_t)Mn * Cn];
__device__ float g_outs[(size_t)Mn * Cn];
__device__ float g_h1  [(size_t)Mn * 512];
__device__ float g_colsum[Bn * Cn];
__device__ float g_sumws [Bn * Hn * Nn];
__device__ float g_rw2   [Bn * Hn * Nn];
__device__ float g_Pi    [Bn * Hn * Nn];
__device__ float g_S   [Bn * Hn];
__device__ float g_num [Bn * Hn];
__device__ float g_attn[Bn * Hn];
__device__ float g_Wc[Cn * Cn];      // out_proj_w @ tssa_out_w
__device__ float g_bc[Cn];           // out_proj_w @ tssa_out_b + out_proj_b
__device__ float g_Wd[512 * Cn];     // ffn1_m @ Wc
__device__ float g_b2[512];          // ffn1_b + ffn1_m @ bc
__device__ float g_Wqv[512 * Cn];    // [Wq+Wk ; Wv] packed, (h d) layout
__device__ float g_bqv[512];

// ---------------- helpers ---------------------------------------------------
__device__ __forceinline__ void mma_tf32(float* d, const uint32_t* a, const uint32_t* b) {
    asm volatile(
        "mma.sync.aligned.m16n8k8.row.col.f32.tf32.tf32.f32 "
        "{%0,%1,%2,%3}, {%4,%5,%6,%7}, {%8,%9}, {%0,%1,%2,%3};\n"
        : "+f"(d[0]), "+f"(d[1]), "+f"(d[2]), "+f"(d[3])
        : "r"(a[0]), "r"(a[1]), "r"(a[2]), "r"(a[3]), "r"(b[0]), "r"(b[1]));
}

__device__ __forceinline__ void cp16(uint32_t saddr, const void* g) {
    asm volatile("cp.async.cg.shared.global [%0], [%1], 16;\n" :: "r"(saddr), "l"(g));
}

// block-wide sum over 256 threads; result valid on thread 0
__device__ __forceinline__ float blockSum256(float v) {
    __shared__ float sm[8];
    #pragma unroll
    for (int o = 16; o > 0; o >>= 1) v += __shfl_xor_sync(0xffffffffu, v, o);
    int lane = threadIdx.x & 31, warp = threadIdx.x >> 5;
    if (lane == 0) sm[warp] = v;
    __syncthreads();
    float r = 0.f;
    if (threadIdx.x < 8) {
        r = sm[threadIdx.x];
        #pragma unroll
        for (int o = 4; o > 0; o >>= 1) r += __shfl_xor_sync(0xffu, r, o);
    }
    __syncthreads();
    return r;
}

// ---------------- tf32 GEMM: C[M,Nout] = A[M,K] @ W[Nout,K]^T + bias (+Rsd) --
// BM=128, BN=128, BK=32, 256 threads (8 warps 2x4), warp tile 64x32.
// cp.async double-buffered. fp32 raw in SMEM; HMMA truncates to tf32.
// AMODE 0: plain A/W (lda=ldw=K).
// AMODE 1: split ffn1 — k<256: A (lda 256) + W (ldw 512); k>=256: A2 (lda 256)
//          + W2 (ldw 256). All cp.async (A2 is pre-scaled by scaleout pass).
// COLSUM: epilogue accumulates per-column sum of C^2 into g_colsum[batch].
static constexpr int STAGE_F = 128 * 36;   // floats per tile per stage

template <int AMODE, bool RES, bool COLSUM>
__global__ __launch_bounds__(256, 2) void gemm_tf32(
    const float* __restrict__ A, const float* __restrict__ A2,
    const float* __restrict__ W, const float* __restrict__ W2,
    const float* __restrict__ bias, const float* __restrict__ Rsd,
    float* __restrict__ C, int K, int Nout)
{
    extern __shared__ float smem[];
    float* Asm = smem;                     // [2][128][36]
    float* Bsm = smem + 2 * STAGE_F;       // [2][128][36]

    const int tid  = threadIdx.x;
    const int m0   = blockIdx.x << 7;
    const int n0   = blockIdx.y << 7;
    const int warp = tid >> 5, lane = tid & 31;
    const int wm = (warp >> 2) << 6;   // 0 or 64
    const int wn = (warp & 3) << 5;    // 0,32,64,96
    const int g  = lane >> 2, tg = lane & 3;

    const uint32_t sA = (uint32_t)__cvta_generic_to_shared(Asm);
    const uint32_t sB = (uint32_t)__cvta_generic_to_shared(Bsm);

    const int lrow = tid >> 3;          // base row, +32 per chunk
    const int lc4  = (tid & 7) << 2;    // 0,4,...,28

    float acc[4][4][4];
    #pragma unroll
    for (int i = 0; i < 4; i++)
        #pragma unroll
        for (int j = 0; j < 4; j++)
            #pragma unroll
            for (int r = 0; r < 4; r++) acc[i][j][r] = 0.f;

    const int KT = K >> 5;

    auto loadStage = [&](int kt, int s) {
        int kb = kt << 5;
        const float* Ap; const float* Wp;
        int kbA, kbW, ldA, ldW;
        if (AMODE == 1) {
            if (kb < 256) { Ap = A;  kbA = kb;       ldA = 256; Wp = W;  kbW = kb;       ldW = 512; }
            else          { Ap = A2; kbA = kb - 256; ldA = 256; Wp = W2; kbW = kb - 256; ldW = 256; }
        } else {
            Ap = A; kbA = kb; ldA = K; Wp = W; kbW = kb; ldW = K;
        }
        #pragma unroll
        for (int i = 0; i < 4; i++) {
            int row = lrow + (i << 5);
            uint32_t so = (uint32_t)((s * STAGE_F + row * 36 + lc4) << 2);
            cp16(sA + so, Ap + (size_t)(m0 + row) * ldA + kbA + lc4);
            cp16(sB + so, Wp + (size_t)(n0 + row) * ldW + kbW + lc4);
        }
        asm volatile("cp.async.commit_group;\n" ::);
    };

    loadStage(0, 0);

    for (int kt = 0; kt < KT; kt++) {
        const int cur = kt & 1;
        if (kt + 1 < KT) {
            loadStage(kt + 1, (kt + 1) & 1);
            asm volatile("cp.async.wait_group 1;\n" ::);
        } else {
            asm volatile("cp.async.wait_group 0;\n" ::);
        }
        __syncthreads();

        const float* Ac = Asm + cur * STAGE_F;
        const float* Bc = Bsm + cur * STAGE_F;

        #pragma unroll
        for (int ks = 0; ks < 4; ks++) {
            const int k0 = ks << 3;
            uint32_t a[4][4], bf[4][2];
            #pragma unroll
            for (int mf = 0; mf < 4; mf++) {
                int r = wm + (mf << 4);
                a[mf][0] = __float_as_uint(Ac[(r + g    ) * 36 + k0 + tg]);
                a[mf][1] = __float_as_uint(Ac[(r + g + 8) * 36 + k0 + tg]);
                a[mf][2] = __float_as_uint(Ac[(r + g    ) * 36 + k0 + tg + 4]);
                a[mf][3] = __float_as_uint(Ac[(r + g + 8) * 36 + k0 + tg + 4]);
            }
            #pragma unroll
            for (int nf = 0; nf < 4; nf++) {
                int c = wn + (nf << 3);
                bf[nf][0] = __float_as_uint(Bc[(c + g) * 36 + k0 + tg]);
                bf[nf][1] = __float_as_uint(Bc[(c + g) * 36 + k0 + tg + 4]);
            }
            #pragma unroll
            for (int mf = 0; mf < 4; mf++)
                #pragma unroll
                for (int nf = 0; nf < 4; nf++)
                    mma_tf32(acc[mf][nf], a[mf], bf[nf]);
        }
        __syncthreads();
    }

    // epilogue
    float* cs = smem;                  // 128-col squared-sum accumulator
    if (COLSUM) {
        if (tid < 128) cs[tid] = 0.f;
        __syncthreads();
    }
    float csl[4][2];
    if (COLSUM) {
        #pragma unroll
        for (int nf = 0; nf < 4; nf++) { csl[nf][0] = 0.f; csl[nf][1] = 0.f; }
    }

    #pragma unroll
    for (int mf = 0; mf < 4; mf++) {
        #pragma unroll
        for (int nf = 0; nf < 4; nf++) {
            int r = m0 + wm + (mf << 4) + g;
            int c = n0 + wn + (nf << 3) + (tg << 1);
            float b0 = bias[c], b1 = bias[c + 1];
            float o0 = acc[mf][nf][0] + b0, o1 = acc[mf][nf][1] + b1;
            float o2 = acc[mf][nf][2] + b0, o3 = acc[mf][nf][3] + b1;
            size_t p0 = (size_t)r * Nout + c;
            size_t p1 = (size_t)(r + 8) * Nout + c;
            if (RES) {
                o0 += Rsd[p0]; o1 += Rsd[p0 + 1];
                o2 += Rsd[p1]; o3 += Rsd[p1 + 1];
            }
            if (COLSUM) {
                csl[nf][0] += o0 * o0 + o2 * o2;
                csl[nf][1] += o1 * o1 + o3 * o3;
            }
            *(float2*)(C + p0) = make_float2(o0, o1);
            *(float2*)(C + p1) = make_float2(o2, o3);
        }
    }

    if (COLSUM) {
        #pragma unroll
        for (int nf = 0; nf < 4; nf++) {
            int cn = wn + (nf << 3) + (tg << 1);
            atomicAdd(&cs[cn], csl[nf][0]);
            atomicAdd(&cs[cn + 1], csl[nf][1]);
        }
        __syncthreads();
        if (tid < 128)
            atomicAdd(&g_colsum[((m0 >> 12) << 8) + n0 + tid], cs[tid]);
    }
}

// ---------------- tiled small fp32 GEMM: C[M,N] = A[M,K] @ B[K,N] -----------
// 64x64 tiles, BK=32, 256 threads, 4x4 per thread. (R12 version — no split-K)
__global__ __launch_bounds__(256) void gemm_small(
    const float* __restrict__ A, int lda,
    const float* __restrict__ B, int ldb,
    float* __restrict__ Cc, int ldc, int K)
{
    __shared__ float As[32][65];
    __shared__ float Bs[32][65];
    int tid = threadIdx.x;
    int m0 = blockIdx.y << 6, n0 = blockIdx.x << 6;
    int ty = tid >> 4, tx = tid & 15;
    float acc[4][4] = {};
    for (int k0 = 0; k0 < K; k0 += 32) {
        #pragma unroll
        for (int i = 0; i < 8; i++) {
            int idx = tid + i * 256;           // 0..2047
            int r = idx >> 5, c = idx & 31;    // A tile: row r, k c
            As[c][r] = A[(size_t)(m0 + r) * lda + k0 + c];
        }
        #pragma unroll
        for (int i = 0; i < 8; i++) {
            int idx = tid + i * 256;
            int r = idx >> 6, c = idx & 63;    // B tile: k r, col c
            Bs[r][c] = B[(size_t)(k0 + r) * ldb + n0 + c];
        }
        __syncthreads();
        #pragma unroll
        for (int kk = 0; kk < 32; kk++) {
            float a[4], b[4];
            #pragma unroll
            for (int i = 0; i < 4; i++) a[i] = As[kk][ty * 4 + i];
            #pragma unroll
            for (int j = 0; j < 4; j++) b[j] = Bs[kk][tx * 4 + j];
            #pragma unroll
            for (int i = 0; i < 4; i++)
                #pragma unroll
                for (int j = 0; j < 4; j++) acc[i][j] += a[i] * b[j];
        }
        __syncthreads();
    }
    #pragma unroll
    for (int i = 0; i < 4; i++)
        #pragma unroll
        for (int j = 0; j < 4; j++)
            Cc[(size_t)(m0 + ty * 4 + i) * ldc + n0 + tx * 4 + j] = acc[i][j];
}

// ---------------- pack [Wq+Wk ; Wv] and biases ------------------------------
__global__ void extract_qkv_kernel(const float* __restrict__ w, const float* __restrict__ b) {
    int idx = blockIdx.x * 256 + threadIdx.x;    // 0..131071
    int c = idx >> 8, k = idx & 255;
    if (c < 256) {
        int h = c >> 6, d = c & 63;
        int base = (h * 192 + d * 3) * 256 + k;
        g_Wqv[(size_t)c * 256 + k] = w[base] + w[base + 256];
        g_Wqv[(size_t)(256 + c) * 256 + k] = w[base + 512];
    }
    if (idx < 256) {
        int h = idx >> 6, d = idx & 63;
        int bb = h * 192 + d * 3;
        g_bqv[idx] = b[bb] + b[bb + 1];
        g_bqv[256 + idx] = b[bb + 2];
    }
}

// ---------------- parallel bias combines (warp-per-output) ------------------
// bc = out_proj_w @ tssa_out_b + out_proj_b   (32 blocks x 8 warps = 256 rows)
__global__ void combine_b_kernel(const float* __restrict__ opw,
                                 const float* __restrict__ ab,
                                 const float* __restrict__ ob) {
    int warp = threadIdx.x >> 5, lane = threadIdx.x & 31;
    int i = blockIdx.x * 8 + warp;
    float s = 0.f;
    #pragma unroll
    for (int k = lane; k < 256; k += 32) s += opw[i * 256 + k] * ab[k];
    #pragma unroll
    for (int o = 16; o > 0; o >>= 1) s += __shfl_xor_sync(0xffffffffu, s, o);
    if (lane == 0) g_bc[i] = s + ob[i];
}
// b2[i] = ffn1_b[i] + sum_k ffn1_w[i][256+k] * bc[k]  (64 blocks x 8 warps)
__global__ void combine_b2_kernel(const float* __restrict__ ffn1w,
                                  const float* __restrict__ ffn1b) {
    int warp = threadIdx.x >> 5, lane = threadIdx.x & 31;
    int i = blockIdx.x * 8 + warp;
    float s = 0.f;
    #pragma unroll
    for (int k = lane; k < 256; k += 32) s += ffn1w[i * 512 + 256 + k] * g_bc[k];
    #pragma unroll
    for (int o = 16; o > 0; o >>= 1) s += __shfl_xor_sync(0xffffffffu, s, o);
    if (lane == 0) g_b2[i] = s + ffn1b[i];
}

// ---------------- zero accumulators (graph-replay safe) ---------------------
__global__ void zero_kernel() {
    int i = blockIdx.x * 256 + threadIdx.x;
    if (i < Bn * Cn) g_colsum[i] = 0.f;
    if (i < Bn * Hn) { g_S[i] = 0.f; g_num[i] = 0.f; }
}

// ---------------- RoPE + (s + v)/3 combine (rope(q)+rope(k) = rope(q+k)) ----
__global__ void rope_kernel(const float* __restrict__ enc) {
    int gid = blockIdx.x * 256 + threadIdx.x;       // (m, h, dpair)
    int dp = gid & 31;
    int h  = (gid >> 5) & 3;
    int m  = gid >> 7;
    int b  = m >> 12, n = m & 4095;

    const float* sv = g_qkv + (size_t)m * 512;
    float2 s = *(const float2*)(sv + h * 64 + dp * 2);
    float2 v = *(const float2*)(sv + 256 + h * 64 + dp * 2);

    size_t eb = ((size_t)b * 4096 + n) * 64 + dp * 2;
    float2 e0 = *(const float2*)(enc + eb);
    float2 e1 = *(const float2*)(enc + 4194304 + eb);  // 16*4096*64

    float sr0 = s.x * e0.x - s.y * e1.x;
    float sr1 = s.y * e0.y + s.x * e1.y;

    const float third = 1.f / 3.f;
    float2 o;
    o.x = (sr0 + v.x) * third;
    o.y = (sr1 + v.y) * third;
    *(float2*)(g_wi + (size_t)m * 256 + h * 64 + dp * 2) = o;
}

// ---------------- per-(row, head) sums (invnorm fused) ----------------------
__global__ void rowsums_kernel() {
    int warp = threadIdx.x >> 5, lane = threadIdx.x & 31;
    int m = blockIdx.x * 8 + warp;
    int b = m >> 12, n = m & 4095;
    const float4* w4 = (const float4*)g_w;
    float4 v0 = w4[(size_t)m * 64 + lane * 2];
    float4 v1 = w4[(size_t)m * 64 + lane * 2 + 1];
    float vals[8] = {v0.x, v0.y, v0.z, v0.w, v1.x, v1.y, v1.z, v1.w};
    int cbase = (b << 8) + lane * 8;
    float s1 = 0.f, s2 = 0.f;
    #pragma unroll
    for (int j = 0; j < 8; j++) {
        float wv = vals[j];
        float iv = 1.f / fmaxf(sqrtf(g_colsum[cbase + j]), 1e-12f);
        s2 += wv * wv;
        float t = wv * iv;
        s1 += t * t;
    }
    #pragma unroll
    for (int o = 4; o > 0; o >>= 1) {
        s1 += __shfl_xor_sync(0xffffffffu, s1, o);
        s2 += __shfl_xor_sync(0xffffffffu, s2, o);
    }
    if ((lane & 7) == 0) {
        int h = lane >> 3;
        g_sumws[((size_t)((b << 2) + h)) * 4096 + n] = s1;
        g_rw2  [((size_t)((b << 2) + h)) * 4096 + n] = s2;
    }
}

// ---------------- Pi = softmax over heads; accumulate S and num -------------
__global__ void pi_kernel(const float* __restrict__ temp) {
    int b = blockIdx.x >> 4;
    int n = ((blockIdx.x & 15) << 8) + threadIdx.x;
    float sw[4], p[4], r2[4];
    #pragma unroll
    for (int h = 0; h < 4; h++) {
        size_t idx = (size_t)((b << 2) + h) * 4096 + n;
        sw[h] = g_sumws[idx] * temp[h];
        r2[h] = g_rw2[idx];
    }
    float mx = fmaxf(fmaxf(sw[0], sw[1]), fmaxf(sw[2], sw[3]));
    float s = 0.f;
    #pragma unroll
    for (int h = 0; h < 4; h++) { p[h] = expf(sw[h] - mx); s += p[h]; }
    float inv = 1.f / s;
    #pragma unroll
    for (int h = 0; h < 4; h++) {
        p[h] *= inv;
        g_Pi[(size_t)((b << 2) + h) * 4096 + n] = p[h];
    }
    for (int h = 0; h < 4; h++) {
        float t1 = blockSum256(p[h]);
        float t2 = blockSum256(p[h] * r2[h]);
        if (threadIdx.x == 0) {
            atomicAdd(&g_S[(b << 2) + h], t1);
            atomicAdd(&g_num[(b << 2) + h], t2);
        }
    }
}

__global__ void attn_kernel() {
    int i = threadIdx.x;
    if (i < Bn * Hn) {
        float d = g_num[i] / (g_S[i] + 1e-8f);
        g_attn[i] = 1.f / (1.f + d);
    }
}

// ---------------- out = -w * Pi * attn --------------------------------------
__global__ void scaleout_kernel() {
    int idx = blockIdx.x * 256 + threadIdx.x;   // float4 index
    int m = idx >> 6, c4 = idx & 63;
    int b = m >> 12, n = m & 4095;
    int h = c4 >> 4;
    float sc = -g_Pi[(size_t)((b << 2) + h) * 4096 + n] * g_attn[(b << 2) + h];
    float4 v = ((const float4*)g_w)[idx];
    v.x *= sc; v.y *= sc; v.z *= sc; v.w *= sc;
    ((float4*)g_outs)[idx] = v;
}

// ---------------- LayerNorm(512) + exact GELU, in place on g_h1 -------------
__global__ void lngelu_kernel(const float* __restrict__ gain, const float* __restrict__ beta) {
    int warp = threadIdx.x >> 5, lane = threadIdx.x & 31;
    int m = blockIdx.x * 8 + warp;
    float4* row = (float4*)(g_h1 + (size_t)m * 512);
    float v[16];
    #pragma unroll
    for (int i = 0; i < 4; i++) {
        float4 t = row[i * 32 + lane];
        v[i * 4 + 0] = t.x; v[i * 4 + 1] = t.y; v[i * 4 + 2] = t.z; v[i * 4 + 3] = t.w;
    }
    float s = 0.f;
    #pragma unroll
    for (int j = 0; j < 16; j++) s += v[j];
    #pragma unroll
    for (int o = 16; o > 0; o >>= 1) s += __shfl_xor_sync(0xffffffffu, s, o);
    float mu = s * (1.f / 512.f);
    float var = 0.f;
    #pragma unroll
    for (int j = 0; j < 16; j++) { float d = v[j] - mu; var += d * d; }
    #pragma unroll
    for (int o = 16; o > 0; o >>= 1) var += __shfl_xor_sync(0xffffffffu, var, o);
    float rstd = rsqrtf(var * (1.f / 512.f) + 1e-5f);
    #pragma unroll
    for (int i = 0; i < 4; i++) {
        float4 gg = ((const float4*)gain)[i * 32 + lane];
        float4 bb = ((const float4*)beta)[i * 32 + lane];
        float gv[4] = {gg.x, gg.y, gg.z, gg.w};
        float bv[4] = {bb.x, bb.y, bb.z, bb.w};
        float4 out;
        float* op = (float*)&out;
        #pragma unroll
        for (int j = 0; j < 4; j++) {
            float ln = (v[i * 4 + j] - mu) * rstd * gv[j] + bv[j];
            op[j] = 0.5f * ln * (1.f + erff(ln * 0.70710678118654752f));
        }
        row[i * 32 + lane] = out;
    }
}

// ---------------- host-side orchestration -----------------------------------
extern "C" void kernel_launch(void* const* d_in, const int* in_sizes, int n_in,
                              void* d_out, int out_size) {
    const float* x       = (const float*)d_in[0];
    const float* enc     = (const float*)d_in[1];
    const float* Wqkv_w  = (const float*)d_in[2];
    const float* Wqkv_b  = (const float*)d_in[3];
    const float* tqkv_w  = (const float*)d_in[4];
    const float* tqkv_b  = (const float*)d_in[5];
    const float* temp    = (const float*)d_in[6];
    const float* tout_w  = (const float*)d_in[7];
    const float* tout_b  = (const float*)d_in[8];
    const float* oproj_w = (const float*)d_in[9];
    const float* oproj_b = (const float*)d_in[10];
    const float* ffn1_w  = (const float*)d_in[11];
    const float* ffn1_b  = (const float*)d_in[12];
    const float* ln_g    = (const float*)d_in[13];
    const float* ln_b    = (const float*)d_in[14];
    const float* ffn2_w  = (const float*)d_in[15];
    const float* ffn2_b  = (const float*)d_in[16];
    float* out = (float*)d_out;

    float *p_qkv, *p_wi, *p_w, *p_outs, *p_h1, *p_Wc, *p_Wd, *p_b2, *p_Wqv, *p_bqv;
    cudaGetSymbolAddress((void**)&p_qkv,  g_qkv);
    cudaGetSymbolAddress((void**)&p_wi,   g_wi);
    cudaGetSymbolAddress((void**)&p_w,    g_w);
    cudaGetSymbolAddress((void**)&p_outs, g_outs);
    cudaGetSymbolAddress((void**)&p_h1,   g_h1);
    cudaGetSymbolAddress((void**)&p_Wc,   g_Wc);
    cudaGetSymbolAddress((void**)&p_Wd,   g_Wd);
    cudaGetSymbolAddress((void**)&p_b2,   g_b2);
    cudaGetSymbolAddress((void**)&p_Wqv,  g_Wqv);
    cudaGetSymbolAddress((void**)&p_bqv,  g_bqv);

    const int SMEM = 4 * STAGE_F * sizeof(float);   // 73728 bytes
    static bool attr_set = false;
    if (!attr_set) {
        cudaFuncSetAttribute(gemm_tf32<0, false, false>, cudaFuncAttributeMaxDynamicSharedMemorySize, SMEM);
        cudaFuncSetAttribute(gemm_tf32<0, false, true >, cudaFuncAttributeMaxDynamicSharedMemorySize, SMEM);
        cudaFuncSetAttribute(gemm_tf32<1, false, false>, cudaFuncAttributeMaxDynamicSharedMemorySize, SMEM);
        cudaFuncSetAttribute(gemm_tf32<0, true,  false>, cudaFuncAttributeMaxDynamicSharedMemorySize, SMEM);
        attr_set = true;
    }

    zero_kernel<<<16, 256>>>();
    extract_qkv_kernel<<<512, 256>>>(Wqkv_w, Wqkv_b);
    // Wc = out_proj_w @ tssa_out_w   (256x256x256, tiled)
    gemm_small<<<dim3(4, 4), 256>>>(oproj_w, 256, tout_w, 256, p_Wc, 256, 256);
    combine_b_kernel<<<32, 256>>>(oproj_w, tout_b, oproj_b);
    // Wd = ffn1_m @ Wc               (512x256x256, tiled; ffn1_m = ffn1_w cols 256..511)
    gemm_small<<<dim3(4, 8), 256>>>(ffn1_w + 256, 512, p_Wc, 256, p_Wd, 256, 256);
    combine_b2_kernel<<<64, 256>>>(ffn1_w, ffn1_b);

    // [s|v] = x @ [Ws;Wv]^T + b     (rope linearity: N=512 instead of 768)
    gemm_tf32<0, false, false><<<dim3(512, 4), 256, SMEM>>>(
        x, nullptr, p_Wqv, nullptr, p_bqv, nullptr, p_qkv, 256, 512);
    // RoPE(s) + v -> w_input
    rope_kernel<<<32768, 256>>>(enc);
    // w = w_input @ tssa_qkv^T + b   (+ fused column sum of w^2)
    gemm_tf32<0, false, true><<<dim3(512, 2), 256, SMEM>>>(
        p_wi, nullptr, tqkv_w, nullptr, tqkv_b, nullptr, p_w, 256, 256);
    // TSSA reductions (invnorm fused into rowsums)
    rowsums_kernel<<<8192, 256>>>();
    pi_kernel<<<256, 256>>>(temp);
    attn_kernel<<<1, 64>>>();
    scaleout_kernel<<<16384, 256>>>();
    // h1 = x @ ffn1_x^T + outs @ Wd^T + b2   (msg GEMM folded; all cp.async)
    gemm_tf32<1, false, false><<<dim3(512, 4), 256, SMEM>>>(
        x, p_outs, ffn1_w, p_Wd, p_b2, nullptr, p_h1, 512, 512);
    // LN + exact GELU in place
    lngelu_kernel<<<8192, 256>>>(ln_g, ln_b);
    // out = x + g @ ffn2^T + b
    gemm_tf32<0, true, false><<<dim3(512, 2), 256, SMEM>>>(
        p_h1, nullptr, ffn2_w, nullptr, ffn2_b, x, out, 512, 256);
}

// round 17
// speedup vs baseline: 1.6417x; 1.0204x over previous
#include <cuda_runtime.h>
#include <cstdint>
#include <cstddef>

static constexpr int Bn = 16;
static constexpr int Nn = 4096;
static constexpr int Cn = 256;
static constexpr int Hn = 4;
static constexpr int Mn = Bn * Nn;   // 65536 rows

// ---------------- scratch (static __device__ per allocation rules) ----------
__device__ float g_qkv [(size_t)Mn * 512];   // [s | v], 512 wide
__device__ float g_wi  [(size_t)Mn * Cn];
__device__ float g_w   [(size_t)Mn * Cn];
__device__ float g_outs[(size_t)Mn * Cn];
__device__ float g_h1  [(size_t)Mn * 512];
__device__ float g_colsum[Bn * Cn];
__device__ float g_sumws [Bn * Hn * Nn];
__device__ float g_rw2   [Bn * Hn * Nn];
__device__ float g_Pi    [Bn * Hn * Nn];
__device__ float g_S   [Bn * Hn];
__device__ float g_num [Bn * Hn];
__device__ float g_attn[Bn * Hn];
__device__ float g_Wc[Cn * Cn];      // out_proj_w @ tssa_out_w
__device__ float g_bc[Cn];           // out_proj_w @ tssa_out_b + out_proj_b
__device__ float g_Wd[512 * Cn];     // ffn1_m @ Wc
__device__ float g_b2[512];          // ffn1_b + ffn1_m @ bc
__device__ float g_Wqv[512 * Cn];    // [Wq+Wk ; Wv] packed, (h d) layout
__device__ float g_bqv[512];

// ---------------- helpers ---------------------------------------------------
__device__ __forceinline__ void mma_tf32(float* d, const uint32_t* a, const uint32_t* b) {
    asm volatile(
        "mma.sync.aligned.m16n8k8.row.col.f32.tf32.tf32.f32 "
        "{%0,%1,%2,%3}, {%4,%5,%6,%7}, {%8,%9}, {%0,%1,%2,%3};\n"
        : "+f"(d[0]), "+f"(d[1]), "+f"(d[2]), "+f"(d[3])
        : "r"(a[0]), "r"(a[1]), "r"(a[2]), "r"(a[3]), "r"(b[0]), "r"(b[1]));
}

__device__ __forceinline__ void cp16(uint32_t saddr, const void* g) {
    asm volatile("cp.async.cg.shared.global [%0], [%1], 16;\n" :: "r"(saddr), "l"(g));
}

// block-wide sum over 256 threads; result valid on thread 0
__device__ __forceinline__ float blockSum256(float v) {
    __shared__ float sm[8];
    #pragma unroll
    for (int o = 16; o > 0; o >>= 1) v += __shfl_xor_sync(0xffffffffu, v, o);
    int lane = threadIdx.x & 31, warp = threadIdx.x >> 5;
    if (lane == 0) sm[warp] = v;
    __syncthreads();
    float r = 0.f;
    if (threadIdx.x < 8) {
        r = sm[threadIdx.x];
        #pragma unroll
        for (int o = 4; o > 0; o >>= 1) r += __shfl_xor_sync(0xffu, r, o);
    }
    __syncthreads();
    return r;
}

// ---------------- tf32 GEMM: C[M,Nout] = A[M,K] @ W[Nout,K]^T + bias (+Rsd) --
// BM=128, BN=128, BK=32, 256 threads (8 warps 2x4), warp tile 64x32.
// 3-stage cp.async pipeline, ONE __syncthreads per k-tile.
// AMODE 0: plain A/W (lda=ldw=K).
// AMODE 1: split ffn1 — k<256: A (lda 256) + W (ldw 512); k>=256: A2 (lda 256)
//          + W2 (ldw 256). All cp.async (A2 is pre-scaled by scaleout pass).
// COLSUM: epilogue accumulates per-column sum of C^2 into g_colsum[batch].
static constexpr int STAGE_F = 128 * 36;                 // floats per tile per stage
static constexpr int SMEM3   = 3 * 2 * STAGE_F * 4;      // 110592 bytes

template <int AMODE, bool RES, bool COLSUM>
__global__ __launch_bounds__(256, 2) void gemm_tf32(
    const float* __restrict__ A, const float* __restrict__ A2,
    const float* __restrict__ W, const float* __restrict__ W2,
    const float* __restrict__ bias, const float* __restrict__ Rsd,
    float* __restrict__ C, int K, int Nout)
{
    extern __shared__ float smem[];
    // layout: stage s -> A at smem + s*2*STAGE_F, B at +STAGE_F
    const int tid  = threadIdx.x;
    const int m0   = blockIdx.x << 7;
    const int n0   = blockIdx.y << 7;
    const int warp = tid >> 5, lane = tid & 31;
    const int wm = (warp >> 2) << 6;   // 0 or 64
    const int wn = (warp & 3) << 5;    // 0,32,64,96
    const int g  = lane >> 2, tg = lane & 3;

    const uint32_t sBase = (uint32_t)__cvta_generic_to_shared(smem);

    const int lrow = tid >> 3;          // base row, +32 per chunk
    const int lc4  = (tid & 7) << 2;    // 0,4,...,28

    float acc[4][4][4];
    #pragma unroll
    for (int i = 0; i < 4; i++)
        #pragma unroll
        for (int j = 0; j < 4; j++)
            #pragma unroll
            for (int r = 0; r < 4; r++) acc[i][j][r] = 0.f;

    const int KT = K >> 5;

    auto loadStage = [&](int kt, int s) {
        int kb = kt << 5;
        const float* Ap; const float* Wp;
        int kbA, kbW, ldA, ldW;
        if (AMODE == 1) {
            if (kb < 256) { Ap = A;  kbA = kb;       ldA = 256; Wp = W;  kbW = kb;       ldW = 512; }
            else          { Ap = A2; kbA = kb - 256; ldA = 256; Wp = W2; kbW = kb - 256; ldW = 256; }
        } else {
            Ap = A; kbA = kb; ldA = K; Wp = W; kbW = kb; ldW = K;
        }
        uint32_t sA = sBase + (uint32_t)(s * 2 * STAGE_F) * 4;
        uint32_t sB = sA + (uint32_t)STAGE_F * 4;
        #pragma unroll
        for (int i = 0; i < 4; i++) {
            int row = lrow + (i << 5);
            uint32_t so = (uint32_t)((row * 36 + lc4) << 2);
            cp16(sA + so, Ap + (size_t)(m0 + row) * ldA + kbA + lc4);
            cp16(sB + so, Wp + (size_t)(n0 + row) * ldW + kbW + lc4);
        }
        asm volatile("cp.async.commit_group;\n" ::);
    };

    loadStage(0, 0);
    loadStage(1, 1);

    for (int kt = 0; kt < KT; kt++) {
        if (kt + 1 < KT) asm volatile("cp.async.wait_group 1;\n" ::);
        else             asm volatile("cp.async.wait_group 0;\n" ::);
        __syncthreads();

        // prefetch 2 tiles ahead into buffer (kt-1)%3 — barrier above proved it drained
        if (kt + 2 < KT) loadStage(kt + 2, (kt + 2) % 3);

        const int cur = kt % 3;
        const float* Ac = smem + cur * 2 * STAGE_F;
        const float* Bc = Ac + STAGE_F;

        #pragma unroll
        for (int ks = 0; ks < 4; ks++) {
            const int k0 = ks << 3;
            uint32_t a[4][4], bf[4][2];
            #pragma unroll
            for (int mf = 0; mf < 4; mf++) {
                int r = wm + (mf << 4);
                a[mf][0] = __float_as_uint(Ac[(r + g    ) * 36 + k0 + tg]);
                a[mf][1] = __float_as_uint(Ac[(r + g + 8) * 36 + k0 + tg]);
                a[mf][2] = __float_as_uint(Ac[(r + g    ) * 36 + k0 + tg + 4]);
                a[mf][3] = __float_as_uint(Ac[(r + g + 8) * 36 + k0 + tg + 4]);
            }
            #pragma unroll
            for (int nf = 0; nf < 4; nf++) {
                int c = wn + (nf << 3);
                bf[nf][0] = __float_as_uint(Bc[(c + g) * 36 + k0 + tg]);
                bf[nf][1] = __float_as_uint(Bc[(c + g) * 36 + k0 + tg + 4]);
            }
            #pragma unroll
            for (int mf = 0; mf < 4; mf++)
                #pragma unroll
                for (int nf = 0; nf < 4; nf++)
                    mma_tf32(acc[mf][nf], a[mf], bf[nf]);
        }
    }
    __syncthreads();   // all compute done before smem reuse below

    // epilogue
    float* cs = smem;                  // 128-col squared-sum accumulator
    if (COLSUM) {
        if (tid < 128) cs[tid] = 0.f;
        __syncthreads();
    }
    float csl[4][2];
    if (COLSUM) {
        #pragma unroll
        for (int nf = 0; nf < 4; nf++) { csl[nf][0] = 0.f; csl[nf][1] = 0.f; }
    }

    #pragma unroll
    for (int mf = 0; mf < 4; mf++) {
        #pragma unroll
        for (int nf = 0; nf < 4; nf++) {
            int r = m0 + wm + (mf << 4) + g;
            int c = n0 + wn + (nf << 3) + (tg << 1);
            float b0 = bias[c], b1 = bias[c + 1];
            float o0 = acc[mf][nf][0] + b0, o1 = acc[mf][nf][1] + b1;
            float o2 = acc[mf][nf][2] + b0, o3 = acc[mf][nf][3] + b1;
            size_t p0 = (size_t)r * Nout + c;
            size_t p1 = (size_t)(r + 8) * Nout + c;
            if (RES) {
                o0 += Rsd[p0]; o1 += Rsd[p0 + 1];
                o2 += Rsd[p1]; o3 += Rsd[p1 + 1];
            }
            if (COLSUM) {
                csl[nf][0] += o0 * o0 + o2 * o2;
                csl[nf][1] += o1 * o1 + o3 * o3;
            }
            *(float2*)(C + p0) = make_float2(o0, o1);
            *(float2*)(C + p1) = make_float2(o2, o3);
        }
    }

    if (COLSUM) {
        #pragma unroll
        for (int nf = 0; nf < 4; nf++) {
            int cn = wn + (nf << 3) + (tg << 1);
            atomicAdd(&cs[cn], csl[nf][0]);
            atomicAdd(&cs[cn + 1], csl[nf][1]);
        }
        __syncthreads();
        if (tid < 128)
            atomicAdd(&g_colsum[((m0 >> 12) << 8) + n0 + tid], cs[tid]);
    }
}

// ---------------- tiled small fp32 GEMM, split-K: C += A @ B ----------------
// 64x64 tiles, BK=32, 256 threads, 4x4 per thread, blockIdx.z = K slice.
// C must be pre-zeroed (done in zero_kernel).
__global__ __launch_bounds__(256) void gemm_small(
    const float* __restrict__ A, int lda,
    const float* __restrict__ B, int ldb,
    float* __restrict__ Cc, int ldc, int K)
{
    __shared__ float As[32][65];
    __shared__ float Bs[32][65];
    int tid = threadIdx.x;
    int m0 = blockIdx.y << 6, n0 = blockIdx.x << 6;
    int kslice = K / gridDim.z;
    int kbeg = blockIdx.z * kslice, kend = kbeg + kslice;
    int ty = tid >> 4, tx = tid & 15;
    float acc[4][4] = {};
    for (int k0 = kbeg; k0 < kend; k0 += 32) {
        #pragma unroll
        for (int i = 0; i < 8; i++) {
            int idx = tid + i * 256;           // 0..2047
            int r = idx >> 5, c = idx & 31;    // A tile: row r, k c
            As[c][r] = A[(size_t)(m0 + r) * lda + k0 + c];
        }
        #pragma unroll
        for (int i = 0; i < 8; i++) {
            int idx = tid + i * 256;
            int r = idx >> 6, c = idx & 63;    // B tile: k r, col c
            Bs[r][c] = B[(size_t)(k0 + r) * ldb + n0 + c];
        }
        __syncthreads();
        #pragma unroll
        for (int kk = 0; kk < 32; kk++) {
            float a[4], b[4];
            #pragma unroll
            for (int i = 0; i < 4; i++) a[i] = As[kk][ty * 4 + i];
            #pragma unroll
            for (int j = 0; j < 4; j++) b[j] = Bs[kk][tx * 4 + j];
            #pragma unroll
            for (int i = 0; i < 4; i++)
                #pragma unroll
                for (int j = 0; j < 4; j++) acc[i][j] += a[i] * b[j];
        }
        __syncthreads();
    }
    #pragma unroll
    for (int i = 0; i < 4; i++)
        #pragma unroll
        for (int j = 0; j < 4; j++)
            atomicAdd(&Cc[(size_t)(m0 + ty * 4 + i) * ldc + n0 + tx * 4 + j], acc[i][j]);
}

// ---------------- pack [Wq+Wk ; Wv] and biases ------------------------------
__global__ void extract_qkv_kernel(const float* __restrict__ w, const float* __restrict__ b) {
    int idx = blockIdx.x * 256 + threadIdx.x;    // 0..131071
    int c = idx >> 8, k = idx & 255;
    if (c < 256) {
        int h = c >> 6, d = c & 63;
        int base = (h * 192 + d * 3) * 256 + k;
        g_Wqv[(size_t)c * 256 + k] = w[base] + w[base + 256];
        g_Wqv[(size_t)(256 + c) * 256 + k] = w[base + 512];
    }
    if (idx < 256) {
        int h = idx >> 6, d = idx & 63;
        int bb = h * 192 + d * 3;
        g_bqv[idx] = b[bb] + b[bb + 1];
        g_bqv[256 + idx] = b[bb + 2];
    }
}

// ---------------- parallel bias combines (warp-per-output) ------------------
__global__ void combine_b_kernel(const float* __restrict__ opw,
                                 const float* __restrict__ ab,
                                 const float* __restrict__ ob) {
    int warp = threadIdx.x >> 5, lane = threadIdx.x & 31;
    int i = blockIdx.x * 8 + warp;
    float s = 0.f;
    #pragma unroll
    for (int k = lane; k < 256; k += 32) s += opw[i * 256 + k] * ab[k];
    #pragma unroll
    for (int o = 16; o > 0; o >>= 1) s += __shfl_xor_sync(0xffffffffu, s, o);
    if (lane == 0) g_bc[i] = s + ob[i];
}
__global__ void combine_b2_kernel(const float* __restrict__ ffn1w,
                                  const float* __restrict__ ffn1b) {
    int warp = threadIdx.x >> 5, lane = threadIdx.x & 31;
    int i = blockIdx.x * 8 + warp;
    float s = 0.f;
    #pragma unroll
    for (int k = lane; k < 256; k += 32) s += ffn1w[i * 512 + 256 + k] * g_bc[k];
    #pragma unroll
    for (int o = 16; o > 0; o >>= 1) s += __shfl_xor_sync(0xffffffffu, s, o);
    if (lane == 0) g_b2[i] = s + ffn1b[i];
}

// ---------------- zero accumulators + split-K outputs -----------------------
__global__ void zero_kernel() {
    int i = blockIdx.x * 256 + threadIdx.x;
    if (i < Bn * Cn) g_colsum[i] = 0.f;
    if (i < Bn * Hn) { g_S[i] = 0.f; g_num[i] = 0.f; }
    if (i < Cn * Cn) g_Wc[i] = 0.f;
    if (i < 512 * Cn) g_Wd[i] = 0.f;
}

// ---------------- RoPE + (s + v)/3 combine (rope(q)+rope(k) = rope(q+k)) ----
__global__ void rope_kernel(const float* __restrict__ enc) {
    int gid = blockIdx.x * 256 + threadIdx.x;       // (m, h, dpair)
    int dp = gid & 31;
    int h  = (gid >> 5) & 3;
    int m  = gid >> 7;
    int b  = m >> 12, n = m & 4095;

    const float* sv = g_qkv + (size_t)m * 512;
    float2 s = *(const float2*)(sv + h * 64 + dp * 2);
    float2 v = *(const float2*)(sv + 256 + h * 64 + dp * 2);

    size_t eb = ((size_t)b * 4096 + n) * 64 + dp * 2;
    float2 e0 = *(const float2*)(enc + eb);
    float2 e1 = *(const float2*)(enc + 4194304 + eb);  // 16*4096*64

    float sr0 = s.x * e0.x - s.y * e1.x;
    float sr1 = s.y * e0.y + s.x * e1.y;

    const float third = 1.f / 3.f;
    float2 o;
    o.x = (sr0 + v.x) * third;
    o.y = (sr1 + v.y) * third;
    *(float2*)(g_wi + (size_t)m * 256 + h * 64 + dp * 2) = o;
}

// ---------------- per-(row, head) sums (invnorm fused) ----------------------
__global__ void rowsums_kernel() {
    int warp = threadIdx.x >> 5, lane = threadIdx.x & 31;
    int m = blockIdx.x * 8 + warp;
    int b = m >> 12, n = m & 4095;
    const float4* w4 = (const float4*)g_w;
    float4 v0 = w4[(size_t)m * 64 + lane * 2];
    float4 v1 = w4[(size_t)m * 64 + lane * 2 + 1];
    float vals[8] = {v0.x, v0.y, v0.z, v0.w, v1.x, v1.y, v1.z, v1.w};
    int cbase = (b << 8) + lane * 8;
    float s1 = 0.f, s2 = 0.f;
    #pragma unroll
    for (int j = 0; j < 8; j++) {
        float wv = vals[j];
        float iv = 1.f / fmaxf(sqrtf(g_colsum[cbase + j]), 1e-12f);
        s2 += wv * wv;
        float t = wv * iv;
        s1 += t * t;
    }
    #pragma unroll
    for (int o = 4; o > 0; o >>= 1) {
        s1 += __shfl_xor_sync(0xffffffffu, s1, o);
        s2 += __shfl_xor_sync(0xffffffffu, s2, o);
    }
    if ((lane & 7) == 0) {
        int h = lane >> 3;
        g_sumws[((size_t)((b << 2) + h)) * 4096 + n] = s1;
        g_rw2  [((size_t)((b << 2) + h)) * 4096 + n] = s2;
    }
}

// ---------------- Pi = softmax over heads; accumulate S and num -------------
__global__ void pi_kernel(const float* __restrict__ temp) {
    int b = blockIdx.x >> 4;
    int n = ((blockIdx.x & 15) << 8) + threadIdx.x;
    float sw[4], p[4], r2[4];
    #pragma unroll
    for (int h = 0; h < 4; h++) {
        size_t idx = (size_t)((b << 2) + h) * 4096 + n;
        sw[h] = g_sumws[idx] * temp[h];
        r2[h] = g_rw2[idx];
    }
    float mx = fmaxf(fmaxf(sw[0], sw[1]), fmaxf(sw[2], sw[3]));
    float s = 0.f;
    #pragma unroll
    for (int h = 0; h < 4; h++) { p[h] = expf(sw[h] - mx); s += p[h]; }
    float inv = 1.f / s;
    #pragma unroll
    for (int h = 0; h < 4; h++) {
        p[h] *= inv;
        g_Pi[(size_t)((b << 2) + h) * 4096 + n] = p[h];
    }
    for (int h = 0; h < 4; h++) {
        float t1 = blockSum256(p[h]);
        float t2 = blockSum256(p[h] * r2[h]);
        if (threadIdx.x == 0) {
            atomicAdd(&g_S[(b << 2) + h], t1);
            atomicAdd(&g_num[(b << 2) + h], t2);
        }
    }
}

__global__ void attn_kernel() {
    int i = threadIdx.x;
    if (i < Bn * Hn) {
        float d = g_num[i] / (g_S[i] + 1e-8f);
        g_attn[i] = 1.f / (1.f + d);
    }
}

// ---------------- out = -w * Pi * attn --------------------------------------
__global__ void scaleout_kernel() {
    int idx = blockIdx.x * 256 + threadIdx.x;   // float4 index
    int m = idx >> 6, c4 = idx & 63;
    int b = m >> 12, n = m & 4095;
    int h = c4 >> 4;
    float sc = -g_Pi[(size_t)((b << 2) + h) * 4096 + n] * g_attn[(b << 2) + h];
    float4 v = ((const float4*)g_w)[idx];
    v.x *= sc; v.y *= sc; v.z *= sc; v.w *= sc;
    ((float4*)g_outs)[idx] = v;
}

// ---------------- LayerNorm(512) + exact GELU, in place on g_h1 -------------
__global__ void lngelu_kernel(const float* __restrict__ gain, const float* __restrict__ beta) {
    int warp = threadIdx.x >> 5, lane = threadIdx.x & 31;
    int m = blockIdx.x * 8 + warp;
    float4* row = (float4*)(g_h1 + (size_t)m * 512);
    float v[16];
    #pragma unroll
    for (int i = 0; i < 4; i++) {
        float4 t = row[i * 32 + lane];
        v[i * 4 + 0] = t.x; v[i * 4 + 1] = t.y; v[i * 4 + 2] = t.z; v[i * 4 + 3] = t.w;
    }
    float s = 0.f;
    #pragma unroll
    for (int j = 0; j < 16; j++) s += v[j];
    #pragma unroll
    for (int o = 16; o > 0; o >>= 1) s += __shfl_xor_sync(0xffffffffu, s, o);
    float mu = s * (1.f / 512.f);
    float var = 0.f;
    #pragma unroll
    for (int j = 0; j < 16; j++) { float d = v[j] - mu; var += d * d; }
    #pragma unroll
    for (int o = 16; o > 0; o >>= 1) var += __shfl_xor_sync(0xffffffffu, var, o);
    float rstd = rsqrtf(var * (1.f / 512.f) + 1e-5f);
    #pragma unroll
    for (int i = 0; i < 4; i++) {
        float4 gg = ((const float4*)gain)[i * 32 + lane];
        float4 bb = ((const float4*)beta)[i * 32 + lane];
        float gv[4] = {gg.x, gg.y, gg.z, gg.w};
        float bv[4] = {bb.x, bb.y, bb.z, bb.w};
        float4 out;
        float* op = (float*)&out;
        #pragma unroll
        for (int j = 0; j < 4; j++) {
            float ln = (v[i * 4 + j] - mu) * rstd * gv[j] + bv[j];
            op[j] = 0.5f * ln * (1.f + erff(ln * 0.70710678118654752f));
        }
        row[i * 32 + lane] = out;
    }
}

// ---------------- host-side orchestration -----------------------------------
extern "C" void kernel_launch(void* const* d_in, const int* in_sizes, int n_in,
                              void* d_out, int out_size) {
    const float* x       = (const float*)d_in[0];
    const float* enc     = (const float*)d_in[1];
    const float* Wqkv_w  = (const float*)d_in[2];
    const float* Wqkv_b  = (const float*)d_in[3];
    const float* tqkv_w  = (const float*)d_in[4];
    const float* tqkv_b  = (const float*)d_in[5];
    const float* temp    = (const float*)d_in[6];
    const float* tout_w  = (const float*)d_in[7];
    const float* tout_b  = (const float*)d_in[8];
    const float* oproj_w = (const float*)d_in[9];
    const float* oproj_b = (const float*)d_in[10];
    const float* ffn1_w  = (const float*)d_in[11];
    const float* ffn1_b  = (const float*)d_in[12];
    const float* ln_g    = (const float*)d_in[13];
    const float* ln_b    = (const float*)d_in[14];
    const float* ffn2_w  = (const float*)d_in[15];
    const float* ffn2_b  = (const float*)d_in[16];
    float* out = (float*)d_out;

    float *p_qkv, *p_wi, *p_w, *p_outs, *p_h1, *p_Wc, *p_Wd, *p_b2, *p_Wqv, *p_bqv;
    cudaGetSymbolAddress((void**)&p_qkv,  g_qkv);
    cudaGetSymbolAddress((void**)&p_wi,   g_wi);
    cudaGetSymbolAddress((void**)&p_w,    g_w);
    cudaGetSymbolAddress((void**)&p_outs, g_outs);
    cudaGetSymbolAddress((void**)&p_h1,   g_h1);
    cudaGetSymbolAddress((void**)&p_Wc,   g_Wc);
    cudaGetSymbolAddress((void**)&p_Wd,   g_Wd);
    cudaGetSymbolAddress((void**)&p_b2,   g_b2);
    cudaGetSymbolAddress((void**)&p_Wqv,  g_Wqv);
    cudaGetSymbolAddress((void**)&p_bqv,  g_bqv);

    static bool attr_set = false;
    if (!attr_set) {
        cudaFuncSetAttribute(gemm_tf32<0, false, false>, cudaFuncAttributeMaxDynamicSharedMemorySize, SMEM3);
        cudaFuncSetAttribute(gemm_tf32<0, false, true >, cudaFuncAttributeMaxDynamicSharedMemorySize, SMEM3);
        cudaFuncSetAttribute(gemm_tf32<1, false, false>, cudaFuncAttributeMaxDynamicSharedMemorySize, SMEM3);
        cudaFuncSetAttribute(gemm_tf32<0, true,  false>, cudaFuncAttributeMaxDynamicSharedMemorySize, SMEM3);
        attr_set = true;
    }

    zero_kernel<<<512, 256>>>();
    extract_qkv_kernel<<<512, 256>>>(Wqkv_w, Wqkv_b);
    // Wc = out_proj_w @ tssa_out_w   (split-K x8, accumulated into zeroed buf)
    gemm_small<<<dim3(4, 4, 8), 256>>>(oproj_w, 256, tout_w, 256, p_Wc, 256, 256);
    combine_b_kernel<<<32, 256>>>(oproj_w, tout_b, oproj_b);
    // Wd = ffn1_m @ Wc               (split-K x8; ffn1_m = ffn1_w cols 256..511)
    gemm_small<<<dim3(4, 8, 8), 256>>>(ffn1_w + 256, 512, p_Wc, 256, p_Wd, 256, 256);
    combine_b2_kernel<<<64, 256>>>(ffn1_w, ffn1_b);

    // [s|v] = x @ [Ws;Wv]^T + b     (rope linearity: N=512 instead of 768)
    gemm_tf32<0, false, false><<<dim3(512, 4), 256, SMEM3>>>(
        x, nullptr, p_Wqv, nullptr, p_bqv, nullptr, p_qkv, 256, 512);
    // RoPE(s) + v -> w_input
    rope_kernel<<<32768, 256>>>(enc);
    // w = w_input @ tssa_qkv^T + b   (+ fused column sum of w^2)
    gemm_tf32<0, false, true><<<dim3(512, 2), 256, SMEM3>>>(
        p_wi, nullptr, tqkv_w, nullptr, tqkv_b, nullptr, p_w, 256, 256);
    // TSSA reductions (invnorm fused into rowsums)
    rowsums_kernel<<<8192, 256>>>();
    pi_kernel<<<256, 256>>>(temp);
    attn_kernel<<<1, 64>>>();
    scaleout_kernel<<<16384, 256>>>();
    // h1 = x @ ffn1_x^T + outs @ Wd^T + b2   (msg GEMM folded; all cp.async)
    gemm_tf32<1, false, false><<<dim3(512, 4), 256, SMEM3>>>(
        x, p_outs, ffn1_w, p_Wd, p_b2, nullptr, p_h1, 512, 512);
    // LN + exact GELU in place
    lngelu_kernel<<<8192, 256>>>(ln_g, ln_b);
    // out = x + g @ ffn2^T + b
    gemm_tf32<0, true, false><<<dim3(512, 2), 256, SMEM3>>>(
        p_h1, nullptr, ffn2_w, nullptr, ffn2_b, x, out, 512, 256);
}